// round 1
// baseline (speedup 1.0000x reference)
#include <cuda_runtime.h>
#include <cstdint>
#include <math.h>

#define HEADS 6
#define NTOK  64
#define DIM   192

static constexpr size_t MAXELEM = (size_t)4096 * 64 * 192;

__device__ float g_q[MAXELEM];
__device__ float g_k[MAXELEM];
__device__ float g_v[MAXELEM];
__device__ float g_t[MAXELEM];
__device__ float g_bias[HEADS * 64 * 64];
__device__ float g_scale[HEADS];

// ---------------- helpers ----------------
__device__ __forceinline__ uint32_t f2tf(float x) {
    uint32_t u;
    asm("cvt.rna.tf32.f32 %0, %1;" : "=r"(u) : "f"(x));
    return u;
}
__device__ __forceinline__ float tf32r(float x) { return __uint_as_float(f2tf(x)); }

__device__ __forceinline__ void mma8(float c[4], const uint32_t a[4], const uint32_t b[2]) {
    asm volatile(
        "mma.sync.aligned.m16n8k8.row.col.f32.tf32.tf32.f32 "
        "{%0,%1,%2,%3}, {%4,%5,%6,%7}, {%8,%9}, {%0,%1,%2,%3};"
        : "+f"(c[0]), "+f"(c[1]), "+f"(c[2]), "+f"(c[3])
        : "r"(a[0]), "r"(a[1]), "r"(a[2]), "r"(a[3]), "r"(b[0]), "r"(b[1]));
}

// ---------------- bias / scale precompute ----------------
__device__ __forceinline__ float slog(float d) {
    float x = d * (8.0f / 7.0f);
    float a = fabsf(x);
    float v = log2f(a + 1.0f) * (1.0f / 3.0f);
    return (x > 0.f) ? v : ((x < 0.f) ? -v : 0.f);
}

__global__ void bias_kernel(const float* __restrict__ ls,
                            const float* __restrict__ fc1w,
                            const float* __restrict__ fc1b,
                            const float* __restrict__ fc2w) {
    __shared__ float tab[225][6];
    int t = threadIdx.x;
    if (t < HEADS) g_scale[t] = expf(fminf(ls[t], 4.6051702f));  // log(100)
    if (t < 225) {
        int i = t / 15, j = t % 15;
        float t0 = slog((float)(j - 7));   // x-feature
        float t1 = slog((float)(i - 7));   // y-feature
        float o[6] = {0.f, 0.f, 0.f, 0.f, 0.f, 0.f};
        for (int n = 0; n < 512; n++) {
            float hv = fmaxf(t0 * fc1w[n] + t1 * fc1w[512 + n] + fc1b[n], 0.f);
            const float* w2 = fc2w + n * 6;
            #pragma unroll
            for (int c = 0; c < 6; c++) o[c] += hv * w2[c];
        }
        #pragma unroll
        for (int c = 0; c < 6; c++) tab[t][c] = o[c];
    }
    __syncthreads();
    for (int e = t; e < HEADS * 4096; e += blockDim.x) {
        int hh = e >> 12;
        int rem = e & 4095;
        int i = rem >> 6, j = rem & 63;
        int dy = (i >> 3) - (j >> 3);
        int dx = (i & 7) - (j & 7);
        int idx = (dy + 7) * 15 + (dx + 7);
        float v = tab[idx][hh];
        g_bias[e] = 16.f / (1.f + expf(-v));
    }
}

// ---------------- TF32 GEMM core: [M x 192] @ [192 x 192] tile (128 x 64) ----------------
__device__ __forceinline__ void gemm_block(const float* __restrict__ A,
                                           const float* __restrict__ W,
                                           const float* __restrict__ bias,
                                           float* __restrict__ out,
                                           int coloff) {
    __shared__ float As[128][36];
    __shared__ float Bs[32][72];
    const int tid = threadIdx.x;
    const int lane = tid & 31;
    const int wid = tid >> 5;
    const int wm = wid & 3;   // 4 warps along M (32 rows each)
    const int wn = wid >> 2;  // 2 warps along N (32 cols each)
    const int lr = lane >> 2;
    const int lc = lane & 3;
    const size_t rowbase = (size_t)blockIdx.x * 128;

    float acc[2][4][4];
    #pragma unroll
    for (int a = 0; a < 2; a++)
        #pragma unroll
        for (int b = 0; b < 4; b++)
            #pragma unroll
            for (int c = 0; c < 4; c++) acc[a][b][c] = 0.f;

    for (int kt = 0; kt < 6; ++kt) {
        #pragma unroll
        for (int j = 0; j < 4; j++) {
            int id = tid + j * 256;             // 0..1023
            int r = id >> 3, c4 = (id & 7) << 2;
            float4 v = *(const float4*)(A + (rowbase + r) * 192 + kt * 32 + c4);
            As[r][c4 + 0] = tf32r(v.x);
            As[r][c4 + 1] = tf32r(v.y);
            As[r][c4 + 2] = tf32r(v.z);
            As[r][c4 + 3] = tf32r(v.w);
        }
        #pragma unroll
        for (int j = 0; j < 2; j++) {
            int id = tid + j * 256;             // 0..511
            int r = id >> 4, c4 = (id & 15) << 2;
            float4 v = *(const float4*)(W + (size_t)(kt * 32 + r) * 192 + coloff + c4);
            Bs[r][c4 + 0] = tf32r(v.x);
            Bs[r][c4 + 1] = tf32r(v.y);
            Bs[r][c4 + 2] = tf32r(v.z);
            Bs[r][c4 + 3] = tf32r(v.w);
        }
        __syncthreads();
        #pragma unroll
        for (int kk = 0; kk < 32; kk += 8) {
            uint32_t af[2][4];
            #pragma unroll
            for (int ms = 0; ms < 2; ms++) {
                int r0 = wm * 32 + ms * 16;
                af[ms][0] = __float_as_uint(As[r0 + lr][kk + lc]);
                af[ms][1] = __float_as_uint(As[r0 + lr + 8][kk + lc]);
                af[ms][2] = __float_as_uint(As[r0 + lr][kk + lc + 4]);
                af[ms][3] = __float_as_uint(As[r0 + lr + 8][kk + lc + 4]);
            }
            #pragma unroll
            for (int ns = 0; ns < 4; ns++) {
                int c0 = wn * 32 + ns * 8;
                uint32_t bf[2];
                bf[0] = __float_as_uint(Bs[kk + lc][c0 + lr]);
                bf[1] = __float_as_uint(Bs[kk + lc + 4][c0 + lr]);
                mma8(acc[0][ns], af[0], bf);
                mma8(acc[1][ns], af[1], bf);
            }
        }
        __syncthreads();
    }
    #pragma unroll
    for (int ms = 0; ms < 2; ms++) {
        #pragma unroll
        for (int ns = 0; ns < 4; ns++) {
            int c0 = coloff + wn * 32 + ns * 8 + lc * 2;
            float b0 = bias ? bias[c0] : 0.f;
            float b1 = bias ? bias[c0 + 1] : 0.f;
            size_t r0 = rowbase + wm * 32 + ms * 16 + lr;
            *(float2*)(out + r0 * 192 + c0) =
                make_float2(acc[ms][ns][0] + b0, acc[ms][ns][1] + b1);
            *(float2*)(out + (r0 + 8) * 192 + c0) =
                make_float2(acc[ms][ns][2] + b0, acc[ms][ns][3] + b1);
        }
    }
}

__global__ void __launch_bounds__(256) qkv_kernel(const float* __restrict__ X,
                                                  const float* __restrict__ qw,
                                                  const float* __restrict__ qb,
                                                  const float* __restrict__ kw,
                                                  const float* __restrict__ vw,
                                                  const float* __restrict__ vb) {
    int sel = blockIdx.y / 3;
    int coloff = (blockIdx.y % 3) * 64;
    if (sel == 0)      gemm_block(X, qw, qb,      g_q, coloff);
    else if (sel == 1) gemm_block(X, kw, nullptr, g_k, coloff);
    else               gemm_block(X, vw, vb,      g_v, coloff);
}

__global__ void __launch_bounds__(256) proj_kernel(const float* __restrict__ pw,
                                                   const float* __restrict__ pb,
                                                   float* __restrict__ out) {
    gemm_block(g_t, pw, pb, out, blockIdx.y * 64);
}

// ---------------- attention: one block per (window, head) ----------------
__global__ void __launch_bounds__(128) attn_kernel(const float* __restrict__ mask, int nW) {
    const int b = blockIdx.x;
    const int h = blockIdx.y;
    __shared__ float qs[64][33];
    __shared__ float ks[64][33];
    __shared__ float vs[64][33];
    __shared__ float Ss[64][65];
    __shared__ float rsum[64];

    const int tid = threadIdx.x;
    const int lane = tid & 31;
    const int wid = tid >> 5;
    const int lr = lane >> 2;
    const int lc = lane & 3;
    const size_t base = (size_t)b * 64 * 192 + h * 32;

    {
        int row = tid >> 1;
        int half = (tid & 1) * 16;
        #pragma unroll
        for (int i = 0; i < 16; i += 4) {
            size_t off = base + (size_t)row * 192 + half + i;
            float4 a = *(const float4*)(g_q + off);
            qs[row][half + i] = a.x; qs[row][half + i + 1] = a.y;
            qs[row][half + i + 2] = a.z; qs[row][half + i + 3] = a.w;
            float4 c = *(const float4*)(g_k + off);
            ks[row][half + i] = c.x; ks[row][half + i + 1] = c.y;
            ks[row][half + i + 2] = c.z; ks[row][half + i + 3] = c.w;
            float4 d = *(const float4*)(g_v + off);
            vs[row][half + i] = tf32r(d.x); vs[row][half + i + 1] = tf32r(d.y);
            vs[row][half + i + 2] = tf32r(d.z); vs[row][half + i + 3] = tf32r(d.w);
        }
    }
    __syncthreads();

    // L2 normalize q (fold in per-head scale) and k; round to tf32
    if (tid < 64) {
        float s = 0.f;
        #pragma unroll
        for (int d = 0; d < 32; d++) { float x = qs[tid][d]; s += x * x; }
        float r = rsqrtf(s) * g_scale[h];
        #pragma unroll
        for (int d = 0; d < 32; d++) qs[tid][d] = tf32r(qs[tid][d] * r);
    } else {
        int rr = tid - 64;
        float s = 0.f;
        #pragma unroll
        for (int d = 0; d < 32; d++) { float x = ks[rr][d]; s += x * x; }
        float r = rsqrtf(s);
        #pragma unroll
        for (int d = 0; d < 32; d++) ks[rr][d] = tf32r(ks[rr][d] * r);
    }
    __syncthreads();

    // S = q_hat @ k_hat^T   (each warp: 16 rows x 64 cols)
    {
        float acc[8][4];
        #pragma unroll
        for (int j = 0; j < 8; j++)
            #pragma unroll
            for (int c = 0; c < 4; c++) acc[j][c] = 0.f;
        int m0 = wid * 16;
        #pragma unroll
        for (int kk = 0; kk < 32; kk += 8) {
            uint32_t af[4];
            af[0] = __float_as_uint(qs[m0 + lr][kk + lc]);
            af[1] = __float_as_uint(qs[m0 + lr + 8][kk + lc]);
            af[2] = __float_as_uint(qs[m0 + lr][kk + lc + 4]);
            af[3] = __float_as_uint(qs[m0 + lr + 8][kk + lc + 4]);
            #pragma unroll
            for (int j = 0; j < 8; j++) {
                uint32_t bf[2];
                bf[0] = __float_as_uint(ks[j * 8 + lr][kk + lc]);
                bf[1] = __float_as_uint(ks[j * 8 + lr][kk + lc + 4]);
                mma8(acc[j], af, bf);
            }
        }
        #pragma unroll
        for (int j = 0; j < 8; j++) {
            Ss[m0 + lr][j * 8 + lc * 2]         = acc[j][0];
            Ss[m0 + lr][j * 8 + lc * 2 + 1]     = acc[j][1];
            Ss[m0 + lr + 8][j * 8 + lc * 2]     = acc[j][2];
            Ss[m0 + lr + 8][j * 8 + lc * 2 + 1] = acc[j][3];
        }
    }
    __syncthreads();

    // + rel_bias + mask, row softmax (division deferred to epilogue)
    if (tid < 64) {
        const int r = tid;
        const float* mrow = mask + ((size_t)(b % nW) * 64 + r) * 64;
        const float* brow = g_bias + h * 4096 + r * 64;
        float mx = -1e30f;
        for (int j = 0; j < 64; j++) {
            float v = Ss[r][j] + brow[j] + mrow[j];
            Ss[r][j] = v;
            mx = fmaxf(mx, v);
        }
        float s = 0.f;
        for (int j = 0; j < 64; j++) {
            float e = __expf(Ss[r][j] - mx);
            s += e;
            Ss[r][j] = tf32r(e);
        }
        rsum[r] = s;
    }
    __syncthreads();

    // O = P @ V   (each warp: 16 rows x 32 cols), scale by 1/rowsum at epilogue
    {
        float acc[4][4];
        #pragma unroll
        for (int j = 0; j < 4; j++)
            #pragma unroll
            for (int c = 0; c < 4; c++) acc[j][c] = 0.f;
        int m0 = wid * 16;
        #pragma unroll
        for (int kk = 0; kk < 64; kk += 8) {
            uint32_t af[4];
            af[0] = __float_as_uint(Ss[m0 + lr][kk + lc]);
            af[1] = __float_as_uint(Ss[m0 + lr + 8][kk + lc]);
            af[2] = __float_as_uint(Ss[m0 + lr][kk + lc + 4]);
            af[3] = __float_as_uint(Ss[m0 + lr + 8][kk + lc + 4]);
            #pragma unroll
            for (int j = 0; j < 4; j++) {
                uint32_t bf[2];
                bf[0] = __float_as_uint(vs[kk + lc][j * 8 + lr]);
                bf[1] = __float_as_uint(vs[kk + lc + 4][j * 8 + lr]);
                mma8(acc[j], af, bf);
            }
        }
        float inv0 = 1.0f / rsum[m0 + lr];
        float inv1 = 1.0f / rsum[m0 + lr + 8];
        size_t ob = (size_t)b * 64 * 192 + h * 32;
        #pragma unroll
        for (int j = 0; j < 4; j++) {
            int c0 = j * 8 + lc * 2;
            *(float2*)(g_t + ob + (size_t)(m0 + lr) * 192 + c0) =
                make_float2(acc[j][0] * inv0, acc[j][1] * inv0);
            *(float2*)(g_t + ob + (size_t)(m0 + lr + 8) * 192 + c0) =
                make_float2(acc[j][2] * inv1, acc[j][3] * inv1);
        }
    }
}

// ---------------- launch ----------------
extern "C" void kernel_launch(void* const* d_in, const int* in_sizes, int n_in,
                              void* d_out, int out_size) {
    const float* hidden = (const float*)d_in[0];
    const float* mask   = (const float*)d_in[1];
    const float* ls     = (const float*)d_in[2];
    const float* fc1w   = (const float*)d_in[3];
    const float* fc1b   = (const float*)d_in[4];
    const float* fc2w   = (const float*)d_in[5];
    const float* qw     = (const float*)d_in[6];
    const float* qb     = (const float*)d_in[7];
    const float* kw     = (const float*)d_in[8];
    const float* vw     = (const float*)d_in[9];
    const float* vb     = (const float*)d_in[10];
    const float* pw     = (const float*)d_in[11];
    const float* pb     = (const float*)d_in[12];
    float* out = (float*)d_out;

    int B  = in_sizes[0] / (64 * 192);
    int nW = in_sizes[1] / (64 * 64);
    int mtiles = (B * 64) / 128;

    bias_kernel<<<1, 256>>>(ls, fc1w, fc1b, fc2w);
    qkv_kernel<<<dim3(mtiles, 9), 256>>>(hidden, qw, qb, kw, vw, vb);
    attn_kernel<<<dim3(B, HEADS), 128>>>(mask, nW);
    proj_kernel<<<dim3(mtiles, 3), 256>>>(pw, pb, out);
}

// round 2
// speedup vs baseline: 1.3201x; 1.3201x over previous
#include <cuda_runtime.h>
#include <cstdint>
#include <math.h>

#define HEADS 6
static constexpr size_t MAXELEM = (size_t)4096 * 64 * 192;

__device__ float g_q[MAXELEM];
__device__ float g_k[MAXELEM];
__device__ float g_v[MAXELEM];
__device__ float g_t[MAXELEM];
__device__ float g_bias[HEADS * 64 * 64];
__device__ float g_scale[HEADS];

// ---------------- helpers ----------------
__device__ __forceinline__ uint32_t f2tf(float x) {
    uint32_t u;
    asm("cvt.rna.tf32.f32 %0, %1;" : "=r"(u) : "f"(x));
    return u;
}
__device__ __forceinline__ float tf32r(float x) { return __uint_as_float(f2tf(x)); }

__device__ __forceinline__ void mma8(float c[4], const uint32_t a[4], const uint32_t b[2]) {
    asm volatile(
        "mma.sync.aligned.m16n8k8.row.col.f32.tf32.tf32.f32 "
        "{%0,%1,%2,%3}, {%4,%5,%6,%7}, {%8,%9}, {%0,%1,%2,%3};"
        : "+f"(c[0]), "+f"(c[1]), "+f"(c[2]), "+f"(c[3])
        : "r"(a[0]), "r"(a[1]), "r"(a[2]), "r"(a[3]), "r"(b[0]), "r"(b[1]));
}

// interleave within groups of 8 so (k, k+4) become adjacent -> LDS.64
__device__ __forceinline__ int perm8(int c) { return ((c & 3) << 1) | ((c >> 2) & 1); }

// ---------------- bias / scale precompute ----------------
__device__ __forceinline__ float slog(float d) {
    float x = d * (8.0f / 7.0f);
    float a = fabsf(x);
    float v = log2f(a + 1.0f) * (1.0f / 3.0f);
    return (x > 0.f) ? v : ((x < 0.f) ? -v : 0.f);
}

__global__ void bias_kernel(const float* __restrict__ ls,
                            const float* __restrict__ fc1w,
                            const float* __restrict__ fc1b,
                            const float* __restrict__ fc2w) {
    __shared__ float tab[225][6];
    int t = threadIdx.x;
    if (t < HEADS) g_scale[t] = expf(fminf(ls[t], 4.6051702f));  // log(100)
    if (t < 225) {
        int i = t / 15, j = t % 15;
        float t0 = slog((float)(j - 7));
        float t1 = slog((float)(i - 7));
        float o[6] = {0.f, 0.f, 0.f, 0.f, 0.f, 0.f};
        for (int n = 0; n < 512; n++) {
            float hv = fmaxf(t0 * fc1w[n] + t1 * fc1w[512 + n] + fc1b[n], 0.f);
            const float* w2 = fc2w + n * 6;
            #pragma unroll
            for (int c = 0; c < 6; c++) o[c] += hv * w2[c];
        }
        #pragma unroll
        for (int c = 0; c < 6; c++) tab[t][c] = o[c];
    }
    __syncthreads();
    for (int e = t; e < HEADS * 4096; e += blockDim.x) {
        int hh = e >> 12;
        int rem = e & 4095;
        int i = rem >> 6, j = rem & 63;
        int dy = (i >> 3) - (j >> 3);
        int dx = (i & 7) - (j & 7);
        int idx = (dy + 7) * 15 + (dx + 7);
        float v = tab[idx][hh];
        g_bias[e] = 16.f / (1.f + expf(-v));
    }
}

// ---------------- TF32 GEMM core ----------------
// As: 128 x 192 (k-interleaved, stride 200). Bt: 64 cols x 32 k (k-interleaved, stride 40).
#define AS_STR 200
#define BT_STR 40
#define GEMM_SMEM ((128 * AS_STR + 64 * BT_STR) * 4)

// mode: 0 = +bias fp32 (proj), 1 = +bias, L2-norm, *scale, tf32 (q),
//       2 = L2-norm, tf32 (k), 3 = +bias, tf32 (v)
__device__ __forceinline__ void gemm_tile(const float* __restrict__ As,
                                          float* __restrict__ Bt,
                                          const float* __restrict__ W,
                                          const float* __restrict__ bias,
                                          float* __restrict__ out,
                                          int coloff, int mode, size_t rowbase) {
    const int tid = threadIdx.x;
    const int lane = tid & 31;
    const int wid = tid >> 5;
    const int wm = wid & 3;
    const int wn = wid >> 2;
    const int lr = lane >> 2;
    const int lc = lane & 3;

    float acc[2][4][4];
    #pragma unroll
    for (int a = 0; a < 2; a++)
        #pragma unroll
        for (int b = 0; b < 4; b++)
            #pragma unroll
            for (int c = 0; c < 4; c++) acc[a][b][c] = 0.f;

    for (int kt = 0; kt < 6; ++kt) {
        #pragma unroll
        for (int j = 0; j < 2; j++) {
            int id = tid + j * 256;            // 0..511
            int r = id >> 4;                   // k-row 0..31
            int c4 = (id & 15) << 2;           // col 0..60
            float4 w4 = *(const float4*)(W + (size_t)(kt * 32 + r) * 192 + coloff + c4);
            int pr = (r & ~7) | perm8(r & 7);
            Bt[(c4 + 0) * BT_STR + pr] = tf32r(w4.x);
            Bt[(c4 + 1) * BT_STR + pr] = tf32r(w4.y);
            Bt[(c4 + 2) * BT_STR + pr] = tf32r(w4.z);
            Bt[(c4 + 3) * BT_STR + pr] = tf32r(w4.w);
        }
        __syncthreads();
        #pragma unroll
        for (int kk = 0; kk < 32; kk += 8) {
            int kbase = kt * 32 + kk;
            uint32_t af[2][4];
            #pragma unroll
            for (int ms = 0; ms < 2; ms++) {
                int r0 = wm * 32 + ms * 16 + lr;
                float2 x0 = *(const float2*)(As + r0 * AS_STR + kbase + lc * 2);
                float2 x1 = *(const float2*)(As + (r0 + 8) * AS_STR + kbase + lc * 2);
                af[ms][0] = __float_as_uint(x0.x);
                af[ms][1] = __float_as_uint(x1.x);
                af[ms][2] = __float_as_uint(x0.y);
                af[ms][3] = __float_as_uint(x1.y);
            }
            #pragma unroll
            for (int ns = 0; ns < 4; ns++) {
                float2 b2 = *(const float2*)(Bt + (wn * 32 + ns * 8 + lr) * BT_STR + kk + lc * 2);
                uint32_t bf[2] = {__float_as_uint(b2.x), __float_as_uint(b2.y)};
                mma8(acc[0][ns], af[0], bf);
                mma8(acc[1][ns], af[1], bf);
            }
        }
        __syncthreads();
    }

    // epilogue
    float scl = (mode == 1) ? g_scale[(coloff >> 5) + wn] : 1.f;
    #pragma unroll
    for (int ms = 0; ms < 2; ms++) {
        float vv[4][4];
        float ssa = 0.f, ssb = 0.f;
        #pragma unroll
        for (int ns = 0; ns < 4; ns++) {
            int c0 = coloff + wn * 32 + ns * 8 + lc * 2;
            float b0 = bias ? bias[c0] : 0.f;
            float b1 = bias ? bias[c0 + 1] : 0.f;
            vv[ns][0] = acc[ms][ns][0] + b0;
            vv[ns][1] = acc[ms][ns][1] + b1;
            vv[ns][2] = acc[ms][ns][2] + b0;
            vv[ns][3] = acc[ms][ns][3] + b1;
            ssa += vv[ns][0] * vv[ns][0] + vv[ns][1] * vv[ns][1];
            ssb += vv[ns][2] * vv[ns][2] + vv[ns][3] * vv[ns][3];
        }
        float ra = 1.f, rb = 1.f;
        if (mode == 1 || mode == 2) {
            ssa += __shfl_xor_sync(0xffffffffu, ssa, 1);
            ssa += __shfl_xor_sync(0xffffffffu, ssa, 2);
            ssb += __shfl_xor_sync(0xffffffffu, ssb, 1);
            ssb += __shfl_xor_sync(0xffffffffu, ssb, 2);
            ra = rsqrtf(ssa) * scl;
            rb = rsqrtf(ssb) * scl;
        }
        size_t r0 = rowbase + wm * 32 + ms * 16 + lr;
        #pragma unroll
        for (int ns = 0; ns < 4; ns++) {
            int c0 = coloff + wn * 32 + ns * 8 + lc * 2;
            float o0 = vv[ns][0] * ra, o1 = vv[ns][1] * ra;
            float o2 = vv[ns][2] * rb, o3 = vv[ns][3] * rb;
            if (mode != 0) { o0 = tf32r(o0); o1 = tf32r(o1); o2 = tf32r(o2); o3 = tf32r(o3); }
            *(float2*)(out + r0 * 192 + c0) = make_float2(o0, o1);
            *(float2*)(out + (r0 + 8) * 192 + c0) = make_float2(o2, o3);
        }
    }
}

__device__ __forceinline__ void load_As(float* __restrict__ As,
                                        const float* __restrict__ A, size_t rowbase) {
    const int tid = threadIdx.x;
    #pragma unroll
    for (int j = 0; j < 24; j++) {
        int id = tid + j * 256;                // 0..6143
        int r = id / 48;
        int c4 = (id % 48) << 2;
        float4 v = *(const float4*)(A + (rowbase + r) * 192 + c4);
        int pb = (c4 & ~7) + ((c4 >> 2) & 1);  // perm8 of c4, stride 2 for consecutive
        As[r * AS_STR + pb + 0] = tf32r(v.x);
        As[r * AS_STR + pb + 2] = tf32r(v.y);
        As[r * AS_STR + pb + 4] = tf32r(v.z);
        As[r * AS_STR + pb + 6] = tf32r(v.w);
    }
}

__global__ void __launch_bounds__(256, 2) qkv_kernel(const float* __restrict__ X,
                                                     const float* __restrict__ qw,
                                                     const float* __restrict__ qb,
                                                     const float* __restrict__ kw,
                                                     const float* __restrict__ vw,
                                                     const float* __restrict__ vb) {
    extern __shared__ float sm[];
    float* As = sm;
    float* Bt = sm + 128 * AS_STR;
    size_t rowbase = (size_t)blockIdx.x * 128;
    load_As(As, X, rowbase);
    __syncthreads();
    #pragma unroll 1
    for (int sel = 0; sel < 3; sel++) {
        const float* W = (sel == 0) ? qw : (sel == 1) ? kw : vw;
        const float* bb = (sel == 0) ? qb : (sel == 1) ? (const float*)nullptr : vb;
        float* out = (sel == 0) ? g_q : (sel == 1) ? g_k : g_v;
        int mode = (sel == 0) ? 1 : (sel == 1) ? 2 : 3;
        #pragma unroll 1
        for (int t = 0; t < 3; t++)
            gemm_tile(As, Bt, W, bb, out, t * 64, mode, rowbase);
    }
}

__global__ void __launch_bounds__(256, 2) proj_kernel(const float* __restrict__ pw,
                                                      const float* __restrict__ pb,
                                                      float* __restrict__ out) {
    extern __shared__ float sm[];
    float* As = sm;
    float* Bt = sm + 128 * AS_STR;
    size_t rowbase = (size_t)blockIdx.x * 128;
    load_As(As, g_t, rowbase);
    __syncthreads();
    #pragma unroll 1
    for (int t = 0; t < 3; t++)
        gemm_tile(As, Bt, pw, pb, out, t * 64, 0, rowbase);
}

// ---------------- attention: one block per (window, head) ----------------
__global__ void __launch_bounds__(128) attn_kernel(const float* __restrict__ mask, int nW) {
    const int b = blockIdx.x;
    const int h = blockIdx.y;
    __shared__ float qs[64][40];   // k-interleaved
    __shared__ float ks[64][40];   // k-interleaved
    __shared__ float vst[32][72];  // V transposed, token-interleaved
    __shared__ float Ss[64][72];   // col-interleaved
    __shared__ float rsum[64];

    const int tid = threadIdx.x;
    const int lane = tid & 31;
    const int wid = tid >> 5;
    const int lr = lane >> 2;
    const int lc = lane & 3;
    const size_t base = (size_t)b * 64 * 192 + h * 32;

    // load q,k,v (already normalized / tf32-rounded by qkv_kernel)
    {
        int row = tid >> 1;
        int chalf = (tid & 1) << 4;
        int ptok = (row & ~7) | perm8(row & 7);
        #pragma unroll
        for (int i = 0; i < 16; i += 4) {
            int c = chalf + i;
            size_t off = base + (size_t)row * 192 + c;
            int pb = (c & ~7) + ((c >> 2) & 1);
            float4 a = *(const float4*)(g_q + off);
            qs[row][pb + 0] = a.x; qs[row][pb + 2] = a.y;
            qs[row][pb + 4] = a.z; qs[row][pb + 6] = a.w;
            float4 kk4 = *(const float4*)(g_k + off);
            ks[row][pb + 0] = kk4.x; ks[row][pb + 2] = kk4.y;
            ks[row][pb + 4] = kk4.z; ks[row][pb + 6] = kk4.w;
            float4 vv4 = *(const float4*)(g_v + off);
            vst[c + 0][ptok] = vv4.x; vst[c + 1][ptok] = vv4.y;
            vst[c + 2][ptok] = vv4.z; vst[c + 3][ptok] = vv4.w;
        }
    }
    __syncthreads();

    const int m0 = wid * 16;

    // S = q_hat @ k_hat^T   (warp: 16 rows x 64 cols), +bias +mask in epilogue
    {
        float acc[8][4];
        #pragma unroll
        for (int j = 0; j < 8; j++)
            #pragma unroll
            for (int c = 0; c < 4; c++) acc[j][c] = 0.f;
        #pragma unroll
        for (int kk = 0; kk < 32; kk += 8) {
            float2 x0 = *(const float2*)&qs[m0 + lr][kk + lc * 2];
            float2 x1 = *(const float2*)&qs[m0 + lr + 8][kk + lc * 2];
            uint32_t af[4] = {__float_as_uint(x0.x), __float_as_uint(x1.x),
                              __float_as_uint(x0.y), __float_as_uint(x1.y)};
            #pragma unroll
            for (int j = 0; j < 8; j++) {
                float2 b2 = *(const float2*)&ks[j * 8 + lr][kk + lc * 2];
                uint32_t bf[2] = {__float_as_uint(b2.x), __float_as_uint(b2.y)};
                mma8(acc[j], af, bf);
            }
        }
        const float* bm = g_bias + h * 4096;
        const float* mk = mask + (size_t)(b % nW) * 4096;
        int r0 = m0 + lr, r1 = m0 + lr + 8;
        int p0 = perm8(lc * 2), p1 = perm8(lc * 2 + 1);
        #pragma unroll
        for (int j = 0; j < 8; j++) {
            int c0 = j * 8 + lc * 2;
            float2 bb0 = *(const float2*)(bm + r0 * 64 + c0);
            float2 mm0 = *(const float2*)(mk + r0 * 64 + c0);
            float2 bb1 = *(const float2*)(bm + r1 * 64 + c0);
            float2 mm1 = *(const float2*)(mk + r1 * 64 + c0);
            Ss[r0][j * 8 + p0] = acc[j][0] + bb0.x + mm0.x;
            Ss[r0][j * 8 + p1] = acc[j][1] + bb0.y + mm0.y;
            Ss[r1][j * 8 + p0] = acc[j][2] + bb1.x + mm1.x;
            Ss[r1][j * 8 + p1] = acc[j][3] + bb1.y + mm1.y;
        }
    }
    __syncthreads();

    // parallel softmax: 2 threads per row, XOR-rotated indexing vs banks
    {
        int row = tid >> 1;
        int seg = (tid & 1) << 5;
        int key = (row ^ (seg >> 1)) & 31;
        float mx = -1e30f;
        #pragma unroll
        for (int i = 0; i < 32; i++) mx = fmaxf(mx, Ss[row][seg + (i ^ key)]);
        mx = fmaxf(mx, __shfl_xor_sync(0xffffffffu, mx, 1));
        float s = 0.f;
        #pragma unroll
        for (int i = 0; i < 32; i++) {
            int c = seg + (i ^ key);
            float e = __expf(Ss[row][c] - mx);
            s += e;
            Ss[row][c] = tf32r(e);
        }
        s += __shfl_xor_sync(0xffffffffu, s, 1);
        if ((tid & 1) == 0) rsum[row] = s;
    }
    __syncthreads();

    // O = P @ V   (warp: 16 rows x 32 cols)
    {
        float o[4][4];
        #pragma unroll
        for (int j = 0; j < 4; j++)
            #pragma unroll
            for (int c = 0; c < 4; c++) o[j][c] = 0.f;
        #pragma unroll
        for (int kk = 0; kk < 64; kk += 8) {
            float2 x0 = *(const float2*)&Ss[m0 + lr][kk + lc * 2];
            float2 x1 = *(const float2*)&Ss[m0 + lr + 8][kk + lc * 2];
            uint32_t af[4] = {__float_as_uint(x0.x), __float_as_uint(x1.x),
                              __float_as_uint(x0.y), __float_as_uint(x1.y)};
            #pragma unroll
            for (int j = 0; j < 4; j++) {
                float2 b2 = *(const float2*)&vst[j * 8 + lr][kk + lc * 2];
                uint32_t bf[2] = {__float_as_uint(b2.x), __float_as_uint(b2.y)};
                mma8(o[j], af, bf);
            }
        }
        float inv0 = 1.0f / rsum[m0 + lr];
        float inv1 = 1.0f / rsum[m0 + lr + 8];
        #pragma unroll
        for (int j = 0; j < 4; j++) {
            int c0 = j * 8 + lc * 2;
            *(float2*)(g_t + base + (size_t)(m0 + lr) * 192 + c0) =
                make_float2(o[j][0] * inv0, o[j][1] * inv0);
            *(float2*)(g_t + base + (size_t)(m0 + lr + 8) * 192 + c0) =
                make_float2(o[j][2] * inv1, o[j][3] * inv1);
        }
    }
}

// ---------------- launch ----------------
extern "C" void kernel_launch(void* const* d_in, const int* in_sizes, int n_in,
                              void* d_out, int out_size) {
    const float* hidden = (const float*)d_in[0];
    const float* mask   = (const float*)d_in[1];
    const float* ls     = (const float*)d_in[2];
    const float* fc1w   = (const float*)d_in[3];
    const float* fc1b   = (const float*)d_in[4];
    const float* fc2w   = (const float*)d_in[5];
    const float* qw     = (const float*)d_in[6];
    const float* qb     = (const float*)d_in[7];
    const float* kw     = (const float*)d_in[8];
    const float* vw     = (const float*)d_in[9];
    const float* vb     = (const float*)d_in[10];
    const float* pw     = (const float*)d_in[11];
    const float* pb     = (const float*)d_in[12];
    float* out = (float*)d_out;

    int B  = in_sizes[0] / (64 * 192);
    int nW = in_sizes[1] / (64 * 64);
    int mtiles = (B * 64) / 128;

    cudaFuncSetAttribute(qkv_kernel, cudaFuncAttributeMaxDynamicSharedMemorySize, GEMM_SMEM);
    cudaFuncSetAttribute(proj_kernel, cudaFuncAttributeMaxDynamicSharedMemorySize, GEMM_SMEM);

    bias_kernel<<<1, 256>>>(ls, fc1w, fc1b, fc2w);
    qkv_kernel<<<mtiles, 256, GEMM_SMEM>>>(hidden, qw, qb, kw, vw, vb);
    attn_kernel<<<dim3(B, HEADS), 128>>>(mask, nW);
    proj_kernel<<<mtiles, 256, GEMM_SMEM>>>(pw, pb, out);
}

// round 4
// speedup vs baseline: 1.8904x; 1.4320x over previous
#include <cuda_runtime.h>
#include <cstdint>
#include <math.h>

#define HEADS 6
static constexpr size_t MAXELEM = (size_t)4096 * 64 * 192;

__device__ float g_q[MAXELEM];
__device__ float g_k[MAXELEM];
__device__ float g_v[MAXELEM];
__device__ float g_t[MAXELEM];
__device__ float g_bias[HEADS * 64 * 64];
__device__ float g_scale[HEADS];

// ---------------- helpers ----------------
__device__ __forceinline__ uint32_t f2tf(float x) {
    uint32_t u;
    asm("cvt.rna.tf32.f32 %0, %1;" : "=r"(u) : "f"(x));
    return u;
}
__device__ __forceinline__ float tf32r(float x) { return __uint_as_float(f2tf(x)); }

__device__ __forceinline__ void mma8(float c[4], const uint32_t a[4], const uint32_t b[2]) {
    asm volatile(
        "mma.sync.aligned.m16n8k8.row.col.f32.tf32.tf32.f32 "
        "{%0,%1,%2,%3}, {%4,%5,%6,%7}, {%8,%9}, {%0,%1,%2,%3};"
        : "+f"(c[0]), "+f"(c[1]), "+f"(c[2]), "+f"(c[3])
        : "r"(a[0]), "r"(a[1]), "r"(a[2]), "r"(a[3]), "r"(b[0]), "r"(b[1]));
}
__device__ __forceinline__ int perm8(int c) { return ((c & 3) << 1) | ((c >> 2) & 1); }

__device__ __forceinline__ uint32_t smem_u32(const void* p) {
    uint32_t a;
    asm("{ .reg .u64 t; cvta.to.shared.u64 t, %1; cvt.u32.u64 %0, t; }" : "=r"(a) : "l"(p));
    return a;
}
__device__ __forceinline__ void cp16(uint32_t dst, const void* src) {
    asm volatile("cp.async.cg.shared.global [%0], [%1], 16;" :: "r"(dst), "l"(src) : "memory");
}
__device__ __forceinline__ void cp_commit() {
    asm volatile("cp.async.commit_group;" ::: "memory");
}
template <int N>
__device__ __forceinline__ void cp_wait() {
    asm volatile("cp.async.wait_group %0;" :: "n"(N) : "memory");
}

// ---------------- bias / scale precompute ----------------
__device__ __forceinline__ float slog(float d) {
    float x = d * (8.0f / 7.0f);
    float a = fabsf(x);
    float v = log2f(a + 1.0f) * (1.0f / 3.0f);
    return (x > 0.f) ? v : ((x < 0.f) ? -v : 0.f);
}

__global__ void bias_kernel(const float* __restrict__ ls,
                            const float* __restrict__ fc1w,
                            const float* __restrict__ fc1b,
                            const float* __restrict__ fc2w) {
    __shared__ float tab[225][6];
    int t = threadIdx.x;
    if (t < HEADS) g_scale[t] = expf(fminf(ls[t], 4.6051702f));
    if (t < 225) {
        int i = t / 15, j = t % 15;
        float t0 = slog((float)(j - 7));
        float t1 = slog((float)(i - 7));
        float o[6] = {0.f, 0.f, 0.f, 0.f, 0.f, 0.f};
        for (int n = 0; n < 512; n++) {
            float hv = fmaxf(t0 * fc1w[n] + t1 * fc1w[512 + n] + fc1b[n], 0.f);
            const float* w2 = fc2w + n * 6;
            #pragma unroll
            for (int c = 0; c < 6; c++) o[c] += hv * w2[c];
        }
        #pragma unroll
        for (int c = 0; c < 6; c++) tab[t][c] = o[c];
    }
    __syncthreads();
    for (int e = t; e < HEADS * 4096; e += blockDim.x) {
        int hh = e >> 12;
        int rem = e & 4095;
        int i = rem >> 6, j = rem & 63;
        int dy = (i >> 3) - (j >> 3);
        int dx = (i & 7) - (j & 7);
        float v = tab[(dy + 7) * 15 + (dx + 7)][hh];
        g_bias[e] = 16.f / (1.f + expf(-v));
    }
}

// ---------------- pipelined TF32 GEMM: one 128x64 tile per block ----------------
#define AS_STR 36   // 36 % 32 == 4 -> lr*36+lc covers 32 distinct banks
#define BS_STR 72   // lc*72+lr covers 32 distinct banks
#define A_ST (128 * AS_STR)          // floats per A stage
#define B_ST (32 * BS_STR)           // floats per B stage
#define GEMM_SMEM ((2 * A_ST + 2 * B_ST) * 4)   // 55296 B

// mode: 0 = +bias (proj/out), 1 = +bias,L2norm,*scale,tf32 (q),
//       2 = L2norm,tf32 (k), 3 = +bias,tf32 (v)
__global__ void __launch_bounds__(256) gemm_kernel(const float* __restrict__ Xin,
                                                   const float* __restrict__ qw,
                                                   const float* __restrict__ kw,
                                                   const float* __restrict__ vw,
                                                   const float* __restrict__ qb,
                                                   const float* __restrict__ vb,
                                                   const float* __restrict__ pw,
                                                   const float* __restrict__ pb,
                                                   float* __restrict__ dout,
                                                   int job) {
    extern __shared__ float sm[];
    float* As = sm;                 // [2][128][AS_STR]
    float* Bs = sm + 2 * A_ST;      // [2][32][BS_STR]
    const uint32_t as_u = smem_u32(sm);
    const uint32_t bs_u = as_u + 2 * A_ST * 4;

    const int tid = threadIdx.x;
    const int lane = tid & 31;
    const int wid = tid >> 5;
    const int wm = wid & 3;
    const int wn = wid >> 2;
    const int lr = lane >> 2;
    const int lc = lane & 3;
    const size_t rowbase = (size_t)blockIdx.x * 128;

    int coloff, mode;
    const float *A, *W, *bias;
    float* out;
    if (job) {
        A = g_t; W = pw; bias = pb; out = dout;
        coloff = blockIdx.y * 64; mode = 0;
    } else {
        A = Xin;
        int sel = blockIdx.y / 3;
        coloff = (blockIdx.y % 3) * 64;
        mode = sel + 1;
        W = (sel == 0) ? qw : (sel == 1) ? kw : vw;
        bias = (sel == 0) ? qb : (sel == 2) ? vb : (const float*)nullptr;
        out = (sel == 0) ? g_q : (sel == 1) ? g_k : g_v;
    }

    // async stage loaders
    auto issueA = [&](int st, int kt) {
        #pragma unroll
        for (int j = 0; j < 4; j++) {
            int id = j * 256 + tid;            // 0..1023
            int r = id >> 3;
            int ch = (id & 7) << 2;            // float col 0..28
            cp16(as_u + (st * A_ST + r * AS_STR + ch) * 4,
                 A + (rowbase + r) * 192 + kt * 32 + ch);
        }
    };
    auto issueB = [&](int st, int kt) {
        #pragma unroll
        for (int j = 0; j < 2; j++) {
            int id = j * 256 + tid;            // 0..511
            int r = id >> 4;
            int ch = (id & 15) << 2;           // float col 0..60
            cp16(bs_u + (st * B_ST + r * BS_STR + ch) * 4,
                 W + (size_t)(kt * 32 + r) * 192 + coloff + ch);
        }
    };

    float acc[2][4][4];
    #pragma unroll
    for (int a = 0; a < 2; a++)
        #pragma unroll
        for (int b = 0; b < 4; b++)
            #pragma unroll
            for (int c = 0; c < 4; c++) acc[a][b][c] = 0.f;

    issueA(0, 0); issueB(0, 0); cp_commit();
    issueA(1, 1); issueB(1, 1); cp_commit();

    #pragma unroll 1
    for (int kt = 0; kt < 6; kt++) {
        if (kt < 5) cp_wait<1>(); else cp_wait<0>();
        __syncthreads();
        const float* Ab = As + (kt & 1) * A_ST;
        const float* Bb = Bs + (kt & 1) * B_ST;
        #pragma unroll
        for (int kk = 0; kk < 32; kk += 8) {
            uint32_t af[2][4];
            #pragma unroll
            for (int ms = 0; ms < 2; ms++) {
                int r0 = wm * 32 + ms * 16 + lr;
                af[ms][0] = f2tf(Ab[r0 * AS_STR + kk + lc]);
                af[ms][1] = f2tf(Ab[(r0 + 8) * AS_STR + kk + lc]);
                af[ms][2] = f2tf(Ab[r0 * AS_STR + kk + lc + 4]);
                af[ms][3] = f2tf(Ab[(r0 + 8) * AS_STR + kk + lc + 4]);
            }
            #pragma unroll
            for (int ns = 0; ns < 4; ns++) {
                int c0 = wn * 32 + ns * 8 + lr;
                uint32_t bf[2];
                bf[0] = f2tf(Bb[(kk + lc) * BS_STR + c0]);
                bf[1] = f2tf(Bb[(kk + lc + 4) * BS_STR + c0]);
                mma8(acc[0][ns], af[0], bf);
                mma8(acc[1][ns], af[1], bf);
            }
        }
        __syncthreads();
        if (kt + 2 < 6) { issueA(kt & 1, kt + 2); issueB(kt & 1, kt + 2); cp_commit(); }
    }

    // epilogue
    float scl = (mode == 1) ? g_scale[(coloff >> 5) + wn] : 1.f;
    #pragma unroll
    for (int ms = 0; ms < 2; ms++) {
        float vv[4][4];
        float ssa = 0.f, ssb = 0.f;
        #pragma unroll
        for (int ns = 0; ns < 4; ns++) {
            int c0 = coloff + wn * 32 + ns * 8 + lc * 2;
            float b0 = bias ? bias[c0] : 0.f;
            float b1 = bias ? bias[c0 + 1] : 0.f;
            vv[ns][0] = acc[ms][ns][0] + b0;
            vv[ns][1] = acc[ms][ns][1] + b1;
            vv[ns][2] = acc[ms][ns][2] + b0;
            vv[ns][3] = acc[ms][ns][3] + b1;
            ssa += vv[ns][0] * vv[ns][0] + vv[ns][1] * vv[ns][1];
            ssb += vv[ns][2] * vv[ns][2] + vv[ns][3] * vv[ns][3];
        }
        float ra = 1.f, rb = 1.f;
        if (mode == 1 || mode == 2) {
            ssa += __shfl_xor_sync(0xffffffffu, ssa, 1);
            ssa += __shfl_xor_sync(0xffffffffu, ssa, 2);
            ssb += __shfl_xor_sync(0xffffffffu, ssb, 1);
            ssb += __shfl_xor_sync(0xffffffffu, ssb, 2);
            ra = rsqrtf(ssa) * scl;
            rb = rsqrtf(ssb) * scl;
        }
        size_t r0 = rowbase + wm * 32 + ms * 16 + lr;
        #pragma unroll
        for (int ns = 0; ns < 4; ns++) {
            int c0 = coloff + wn * 32 + ns * 8 + lc * 2;
            float o0 = vv[ns][0] * ra, o1 = vv[ns][1] * ra;
            float o2 = vv[ns][2] * rb, o3 = vv[ns][3] * rb;
            if (mode != 0) { o0 = tf32r(o0); o1 = tf32r(o1); o2 = tf32r(o2); o3 = tf32r(o3); }
            *(float2*)(out + r0 * 192 + c0) = make_float2(o0, o1);
            *(float2*)(out + (r0 + 8) * 192 + c0) = make_float2(o2, o3);
        }
    }
}

// ---------------- attention: one block per (window, head) ----------------
__global__ void __launch_bounds__(128) attn_kernel(const float* __restrict__ mask, int nW) {
    const int b = blockIdx.x;
    const int h = blockIdx.y;
    __shared__ float qs[64][40];
    __shared__ float ks[64][40];
    __shared__ float vst[32][72];
    __shared__ float Ss[64][72];
    __shared__ float rsum[64];

    const int tid = threadIdx.x;
    const int lane = tid & 31;
    const int wid = tid >> 5;
    const int lr = lane >> 2;
    const int lc = lane & 3;
    const size_t base = (size_t)b * 64 * 192 + h * 32;

    {
        int row = tid >> 1;
        int chalf = (tid & 1) << 4;
        int ptok = (row & ~7) | perm8(row & 7);
        #pragma unroll
        for (int i = 0; i < 16; i += 4) {
            int c = chalf + i;
            size_t off = base + (size_t)row * 192 + c;
            int pb = (c & ~7) + ((c >> 2) & 1);
            float4 a = *(const float4*)(g_q + off);
            qs[row][pb + 0] = a.x; qs[row][pb + 2] = a.y;
            qs[row][pb + 4] = a.z; qs[row][pb + 6] = a.w;
            float4 kk4 = *(const float4*)(g_k + off);
            ks[row][pb + 0] = kk4.x; ks[row][pb + 2] = kk4.y;
            ks[row][pb + 4] = kk4.z; ks[row][pb + 6] = kk4.w;
            float4 vv4 = *(const float4*)(g_v + off);
            vst[c + 0][ptok] = vv4.x; vst[c + 1][ptok] = vv4.y;
            vst[c + 2][ptok] = vv4.z; vst[c + 3][ptok] = vv4.w;
        }
    }
    __syncthreads();

    const int m0 = wid * 16;

    {
        float acc[8][4];
        #pragma unroll
        for (int j = 0; j < 8; j++)
            #pragma unroll
            for (int c = 0; c < 4; c++) acc[j][c] = 0.f;
        #pragma unroll
        for (int kk = 0; kk < 32; kk += 8) {
            float2 x0 = *(const float2*)&qs[m0 + lr][kk + lc * 2];
            float2 x1 = *(const float2*)&qs[m0 + lr + 8][kk + lc * 2];
            uint32_t af[4] = {__float_as_uint(x0.x), __float_as_uint(x1.x),
                              __float_as_uint(x0.y), __float_as_uint(x1.y)};
            #pragma unroll
            for (int j = 0; j < 8; j++) {
                float2 b2 = *(const float2*)&ks[j * 8 + lr][kk + lc * 2];
                uint32_t bf[2] = {__float_as_uint(b2.x), __float_as_uint(b2.y)};
                mma8(acc[j], af, bf);
            }
        }
        const float* bm = g_bias + h * 4096;
        const float* mk = mask + (size_t)(b % nW) * 4096;
        int r0 = m0 + lr, r1 = m0 + lr + 8;
        int p0 = perm8(lc * 2), p1 = perm8(lc * 2 + 1);
        #pragma unroll
        for (int j = 0; j < 8; j++) {
            int c0 = j * 8 + lc * 2;
            float2 bb0 = *(const float2*)(bm + r0 * 64 + c0);
            float2 mm0 = *(const float2*)(mk + r0 * 64 + c0);
            float2 bb1 = *(const float2*)(bm + r1 * 64 + c0);
            float2 mm1 = *(const float2*)(mk + r1 * 64 + c0);
            Ss[r0][j * 8 + p0] = acc[j][0] + bb0.x + mm0.x;
            Ss[r0][j * 8 + p1] = acc[j][1] + bb0.y + mm0.y;
            Ss[r1][j * 8 + p0] = acc[j][2] + bb1.x + mm1.x;
            Ss[r1][j * 8 + p1] = acc[j][3] + bb1.y + mm1.y;
        }
    }
    __syncthreads();

    {
        int row = tid >> 1;
        int seg = (tid & 1) << 5;
        int key = (row ^ (seg >> 1)) & 31;
        float mx = -1e30f;
        #pragma unroll
        for (int i = 0; i < 32; i++) mx = fmaxf(mx, Ss[row][seg + (i ^ key)]);
        mx = fmaxf(mx, __shfl_xor_sync(0xffffffffu, mx, 1));
        float s = 0.f;
        #pragma unroll
        for (int i = 0; i < 32; i++) {
            int c = seg + (i ^ key);
            float e = __expf(Ss[row][c] - mx);
            s += e;
            Ss[row][c] = tf32r(e);
        }
        s += __shfl_xor_sync(0xffffffffu, s, 1);
        if ((tid & 1) == 0) rsum[row] = s;
    }
    __syncthreads();

    {
        float o[4][4];
        #pragma unroll
        for (int j = 0; j < 4; j++)
            #pragma unroll
            for (int c = 0; c < 4; c++) o[j][c] = 0.f;
        #pragma unroll
        for (int kk = 0; kk < 64; kk += 8) {
            float2 x0 = *(const float2*)&Ss[m0 + lr][kk + lc * 2];
            float2 x1 = *(const float2*)&Ss[m0 + lr + 8][kk + lc * 2];
            uint32_t af[4] = {__float_as_uint(x0.x), __float_as_uint(x1.x),
                              __float_as_uint(x0.y), __float_as_uint(x1.y)};
            #pragma unroll
            for (int j = 0; j < 4; j++) {
                float2 b2 = *(const float2*)&vst[j * 8 + lr][kk + lc * 2];
                uint32_t bf[2] = {__float_as_uint(b2.x), __float_as_uint(b2.y)};
                mma8(o[j], af, bf);
            }
        }
        float inv0 = 1.0f / rsum[m0 + lr];
        float inv1 = 1.0f / rsum[m0 + lr + 8];
        #pragma unroll
        for (int j = 0; j < 4; j++) {
            int c0 = j * 8 + lc * 2;
            *(float2*)(g_t + base + (size_t)(m0 + lr) * 192 + c0) =
                make_float2(o[j][0] * inv0, o[j][1] * inv0);
            *(float2*)(g_t + base + (size_t)(m0 + lr + 8) * 192 + c0) =
                make_float2(o[j][2] * inv1, o[j][3] * inv1);
        }
    }
}

// ---------------- launch ----------------
extern "C" void kernel_launch(void* const* d_in, const int* in_sizes, int n_in,
                              void* d_out, int out_size) {
    const float* hidden = (const float*)d_in[0];
    const float* mask   = (const float*)d_in[1];
    const float* ls     = (const float*)d_in[2];
    const float* fc1w   = (const float*)d_in[3];
    const float* fc1b   = (const float*)d_in[4];
    const float* fc2w   = (const float*)d_in[5];
    const float* qw     = (const float*)d_in[6];
    const float* qb     = (const float*)d_in[7];
    const float* kw     = (const float*)d_in[8];
    const float* vw     = (const float*)d_in[9];
    const float* vb     = (const float*)d_in[10];
    const float* pw     = (const float*)d_in[11];
    const float* pb     = (const float*)d_in[12];
    float* out = (float*)d_out;

    int B  = in_sizes[0] / (64 * 192);
    int nW = in_sizes[1] / (64 * 64);
    int mtiles = (B * 64) / 128;

    cudaFuncSetAttribute(gemm_kernel, cudaFuncAttributeMaxDynamicSharedMemorySize, GEMM_SMEM);

    bias_kernel<<<1, 256>>>(ls, fc1w, fc1b, fc2w);
    gemm_kernel<<<dim3(mtiles, 9), 256, GEMM_SMEM>>>(hidden, qw, kw, vw, qb, vb, pw, pb, out, 0);
    attn_kernel<<<dim3(B, HEADS), 128>>>(mask, nW);
    gemm_kernel<<<dim3(mtiles, 3), 256, GEMM_SMEM>>>(hidden, qw, kw, vw, qb, vb, pw, pb, out, 1);
}